// round 7
// baseline (speedup 1.0000x reference)
#include <cuda_runtime.h>
#include <cuda_fp16.h>

// Problem constants (fixed by reference setup_inputs)
#define B_  8
#define C_  3
#define H_  1024
#define W_  1024
#define HO_ 256
#define WO_ 256
#define KS_ 3
#define KK_ (KS_*KS_)    // 9
#define SCALE_ 4
#define HP_ (H_ + 2)     // padded 1026
#define WP_ (W_ + 2)
#define PLANE_ (H_*W_)   // 1M

// fp16 NHWC4 scratch: (B, H, W) pixels of 8B (half c0,c1,c2,pad) = 67.1 MB
__device__ uint4 g_img_h4[B_ * H_ * 512];

// ---------------------------------------------------------------------------
// Pre-pass (one batch): NCHW fp32 -> NHWC4 fp16. 4 px/thread, coalesced.
// ---------------------------------------------------------------------------
__global__ __launch_bounds__(256)
void nchw_to_nhwc4h_kernel(const float* __restrict__ img, int b)
{
    const int t   = blockIdx.x * blockDim.x + threadIdx.x;  // 0 .. H*W/4-1
    const int rem = t * 4;

    const float* base = img + (long long)b * 3 * PLANE_ + rem;
    const float4 c0 = *(const float4*)(base);
    const float4 c1 = *(const float4*)(base + PLANE_);
    const float4 c2 = *(const float4*)(base + 2 * PLANE_);

    __half2 a0 = __floats2half2_rn(c0.x, c1.x);
    __half2 a1 = __floats2half2_rn(c2.x, 0.f);
    __half2 b0 = __floats2half2_rn(c0.y, c1.y);
    __half2 b1 = __floats2half2_rn(c2.y, 0.f);
    __half2 d0 = __floats2half2_rn(c0.z, c1.z);
    __half2 d1 = __floats2half2_rn(c2.z, 0.f);
    __half2 e0 = __floats2half2_rn(c0.w, c1.w);
    __half2 e1 = __floats2half2_rn(c2.w, 0.f);

    uint4 v0, v1;
    v0.x = *(unsigned*)&a0;  v0.y = *(unsigned*)&a1;
    v0.z = *(unsigned*)&b0;  v0.w = *(unsigned*)&b1;
    v1.x = *(unsigned*)&d0;  v1.y = *(unsigned*)&d1;
    v1.z = *(unsigned*)&e0;  v1.w = *(unsigned*)&e1;

    uint4* dst = g_img_h4 + ((size_t)b << 19) + (rem >> 1);
    dst[0] = v0;
    dst[1] = v1;
}

// reflect-map a padded index (0..n+1) to original index (0..n-1), pad=1
__device__ __forceinline__ int reflect_map(int i, int n) {
    int j = i - 1;
    j = (j < 0) ? -j : j;
    j = (j >= n) ? (2 * n - 2 - j) : j;
    return j;
}

// ---------------------------------------------------------------------------
// Main pass (one batch): gather half4 corners, fp32 accumulate. (R5 body)
// ---------------------------------------------------------------------------
__global__ __launch_bounds__(256, 5)
void adaptive_downsample_kernel(
    const float* __restrict__ kernels,    // (B,9,HO,WO)
    const float* __restrict__ offs_h,     // (B,9,HO,WO)
    const float* __restrict__ offs_v,     // (B,9,HO,WO)
    const float* __restrict__ offset_unit,// (1,)
    float* __restrict__ out,              // (B,C,HO,WO)
    int b)
{
    const int ow = blockIdx.x * blockDim.x + threadIdx.x;  // 0..255
    const int oh = blockIdx.y * blockDim.y + threadIdx.y;  // 0..255

    const float ou = __ldg(offset_unit);

    const float cy = ((float)oh + 0.5f) * (float)SCALE_ - 0.5f;
    const float cx = ((float)ow + 0.5f) * (float)SCALE_ - 0.5f;

    const int pix   = oh * WO_ + ow;
    const int plane = HO_ * WO_;                 // 65536
    const int auxb  = b * KK_ * plane + pix;

    const uint2* imgb = (const uint2*)g_img_h4 + ((size_t)b << 20);

    float acc0 = 0.f, acc1 = 0.f, acc2 = 0.f;

    #pragma unroll
    for (int k = 0; k < KK_; ++k) {
        const float kw  = __ldg(kernels + auxb + k * plane);
        const float ovv = __ldg(offs_v  + auxb + k * plane);
        const float ohh = __ldg(offs_h  + auxb + k * plane);

        const float py = cy + (float)(k / KS_) + ovv * ou;
        const float px = cx + (float)(k % KS_) + ohh * ou;

        const float y0f = floorf(py);
        const float x0f = floorf(px);
        const float beta  = py - y0f;
        const float alpha = px - x0f;

        int y0 = (int)y0f;  y0 = min(max(y0, 0), HP_ - 1);
        int y1 = min(y0 + 1, HP_ - 1);
        int x0 = (int)x0f;  x0 = min(max(x0, 0), WP_ - 1);
        int x1 = min(x0 + 1, WP_ - 1);

        const int ry0 = reflect_map(y0, H_);
        const int ry1 = reflect_map(y1, H_);
        const int rx0 = reflect_map(x0, W_);
        const int rx1 = reflect_map(x1, W_);

        const float w00 = (1.f - alpha) * (1.f - beta) * kw;
        const float w01 = alpha * (1.f - beta) * kw;
        const float w10 = (1.f - alpha) * beta * kw;
        const float w11 = alpha * beta * kw;

        const int i00 = (ry0 << 10) + rx0;
        const int i01 = (ry0 << 10) + rx1;
        const int i10 = (ry1 << 10) + rx0;
        const int i11 = (ry1 << 10) + rx1;

        {
            const uint2 v = __ldg(imgb + i00);
            const float2 lo = __half22float2(*(__half2*)&v.x);
            const float2 hi = __half22float2(*(__half2*)&v.y);
            acc0 = fmaf(w00, lo.x, acc0);
            acc1 = fmaf(w00, lo.y, acc1);
            acc2 = fmaf(w00, hi.x, acc2);
        }
        {
            const uint2 v = __ldg(imgb + i01);
            const float2 lo = __half22float2(*(__half2*)&v.x);
            const float2 hi = __half22float2(*(__half2*)&v.y);
            acc0 = fmaf(w01, lo.x, acc0);
            acc1 = fmaf(w01, lo.y, acc1);
            acc2 = fmaf(w01, hi.x, acc2);
        }
        {
            const uint2 v = __ldg(imgb + i10);
            const float2 lo = __half22float2(*(__half2*)&v.x);
            const float2 hi = __half22float2(*(__half2*)&v.y);
            acc0 = fmaf(w10, lo.x, acc0);
            acc1 = fmaf(w10, lo.y, acc1);
            acc2 = fmaf(w10, hi.x, acc2);
        }
        {
            const uint2 v = __ldg(imgb + i11);
            const float2 lo = __half22float2(*(__half2*)&v.x);
            const float2 hi = __half22float2(*(__half2*)&v.y);
            acc0 = fmaf(w11, lo.x, acc0);
            acc1 = fmaf(w11, lo.y, acc1);
            acc2 = fmaf(w11, hi.x, acc2);
        }
    }

    const int ob = b * C_ * plane + pix;
    out[ob]             = acc0;
    out[ob + plane]     = acc1;
    out[ob + 2 * plane] = acc2;
}

extern "C" void kernel_launch(void* const* d_in, const int* in_sizes, int n_in,
                              void* d_out, int out_size) {
    const float* img     = (const float*)d_in[0];
    const float* kernels = (const float*)d_in[1];
    const float* offs_h  = (const float*)d_in[2];
    const float* offs_v  = (const float*)d_in[3];
    const float* ou      = (const float*)d_in[4];
    float* out = (float*)d_out;

    // One-time creation of side stream + events (first call is the
    // uncaptured correctness run; captured calls only record/wait/launch).
    static cudaStream_t s1 = nullptr;
    static cudaEvent_t evPre[B_];
    static cudaEvent_t evDone = nullptr;
    if (s1 == nullptr) {
        cudaStreamCreateWithFlags(&s1, cudaStreamNonBlocking);
        for (int i = 0; i < B_; ++i)
            cudaEventCreateWithFlags(&evPre[i], cudaEventDisableTiming);
        cudaEventCreateWithFlags(&evDone, cudaEventDisableTiming);
    }

    const int pre_blocks = PLANE_ / 4 / 256;   // 1024 per batch
    dim3 mblock(32, 8, 1);
    dim3 mgrid(WO_ / 32, HO_ / 8, 1);

    // Batch pipeline: pre(b) on capture stream (0), main(b) on s1 gated by
    // an event — pre(b+1) overlaps main(b).
    for (int b = 0; b < B_; ++b) {
        nchw_to_nhwc4h_kernel<<<pre_blocks, 256, 0, 0>>>(img, b);
        cudaEventRecord(evPre[b], 0);
        cudaStreamWaitEvent(s1, evPre[b], 0);
        adaptive_downsample_kernel<<<mgrid, mblock, 0, s1>>>(
            kernels, offs_h, offs_v, ou, out, b);
    }
    cudaEventRecord(evDone, s1);
    cudaStreamWaitEvent(0, evDone, 0);
}

// round 10
// speedup vs baseline: 1.2731x; 1.2731x over previous
#include <cuda_runtime.h>
#include <cuda_fp16.h>

// Problem constants (fixed by reference setup_inputs)
#define B_  8
#define C_  3
#define H_  1024
#define W_  1024
#define HO_ 256
#define WO_ 256
#define KS_ 3
#define KK_ (KS_*KS_)    // 9
#define SCALE_ 4
#define HP_ (H_ + 2)     // padded 1026
#define WP_ (W_ + 2)
#define PLANE_ (H_*W_)   // 1M
#define BCHUNK_ 4        // batches per pipeline chunk

// fp16 NHWC4 scratch: (B, H, W) pixels of 8B (half c0,c1,c2,pad) = 67.1 MB
__device__ uint4 g_img_h4[B_ * H_ * 512];

// ---------------------------------------------------------------------------
// Pre-pass (BCHUNK_ batches): NCHW fp32 -> NHWC4 fp16. 4 px/thread.
// ---------------------------------------------------------------------------
__global__ __launch_bounds__(256)
void nchw_to_nhwc4h_kernel(const float* __restrict__ img, int b0)
{
    const int t   = blockIdx.x * blockDim.x + threadIdx.x;  // 0 .. BCHUNK_*H*W/4-1
    const int px  = t * 4;
    const int b   = b0 + (px >> 20);
    const int rem = px & (PLANE_ - 1);

    const float* base = img + (long long)b * 3 * PLANE_ + rem;
    const float4 c0 = *(const float4*)(base);
    const float4 c1 = *(const float4*)(base + PLANE_);
    const float4 c2 = *(const float4*)(base + 2 * PLANE_);

    __half2 a0 = __floats2half2_rn(c0.x, c1.x);
    __half2 a1 = __floats2half2_rn(c2.x, 0.f);
    __half2 b0h = __floats2half2_rn(c0.y, c1.y);
    __half2 b1h = __floats2half2_rn(c2.y, 0.f);
    __half2 d0 = __floats2half2_rn(c0.z, c1.z);
    __half2 d1 = __floats2half2_rn(c2.z, 0.f);
    __half2 e0 = __floats2half2_rn(c0.w, c1.w);
    __half2 e1 = __floats2half2_rn(c2.w, 0.f);

    uint4 v0, v1;
    v0.x = *(unsigned*)&a0;   v0.y = *(unsigned*)&a1;
    v0.z = *(unsigned*)&b0h;  v0.w = *(unsigned*)&b1h;
    v1.x = *(unsigned*)&d0;   v1.y = *(unsigned*)&d1;
    v1.z = *(unsigned*)&e0;   v1.w = *(unsigned*)&e1;

    uint4* dst = g_img_h4 + ((size_t)b << 19) + ((rem >> 1) & 0x7FFFF);
    dst[0] = v0;
    dst[1] = v1;
}

// reflect-map a padded index (0..n+1) to original index (0..n-1), pad=1
__device__ __forceinline__ int reflect_map(int i, int n) {
    int j = i - 1;
    j = (j < 0) ? -j : j;
    j = (j >= n) ? (2 * n - 2 - j) : j;
    return j;
}

// ---------------------------------------------------------------------------
// Main pass (BCHUNK_ batches): gather half4 corners, fp32 accumulate.
// ---------------------------------------------------------------------------
__global__ __launch_bounds__(256, 5)
void adaptive_downsample_kernel(
    const float* __restrict__ kernels,    // (B,9,HO,WO)
    const float* __restrict__ offs_h,     // (B,9,HO,WO)
    const float* __restrict__ offs_v,     // (B,9,HO,WO)
    const float* __restrict__ offset_unit,// (1,)
    float* __restrict__ out,              // (B,C,HO,WO)
    int b0)
{
    const int ow = blockIdx.x * blockDim.x + threadIdx.x;  // 0..255
    const int oh = blockIdx.y * blockDim.y + threadIdx.y;  // 0..255
    const int b  = b0 + blockIdx.z;

    const float ou = __ldg(offset_unit);

    const float cy = ((float)oh + 0.5f) * (float)SCALE_ - 0.5f;
    const float cx = ((float)ow + 0.5f) * (float)SCALE_ - 0.5f;

    const int pix   = oh * WO_ + ow;
    const int plane = HO_ * WO_;                 // 65536
    const int auxb  = b * KK_ * plane + pix;

    const uint2* imgb = (const uint2*)g_img_h4 + ((size_t)b << 20);

    float acc0 = 0.f, acc1 = 0.f, acc2 = 0.f;

    #pragma unroll
    for (int k = 0; k < KK_; ++k) {
        const float kw  = __ldg(kernels + auxb + k * plane);
        const float ovv = __ldg(offs_v  + auxb + k * plane);
        const float ohh = __ldg(offs_h  + auxb + k * plane);

        const float py = cy + (float)(k / KS_) + ovv * ou;
        const float px = cx + (float)(k % KS_) + ohh * ou;

        const float y0f = floorf(py);
        const float x0f = floorf(px);
        const float beta  = py - y0f;
        const float alpha = px - x0f;

        int y0 = (int)y0f;  y0 = min(max(y0, 0), HP_ - 1);
        int y1 = min(y0 + 1, HP_ - 1);
        int x0 = (int)x0f;  x0 = min(max(x0, 0), WP_ - 1);
        int x1 = min(x0 + 1, WP_ - 1);

        const int ry0 = reflect_map(y0, H_);
        const int ry1 = reflect_map(y1, H_);
        const int rx0 = reflect_map(x0, W_);
        const int rx1 = reflect_map(x1, W_);

        const float w00 = (1.f - alpha) * (1.f - beta) * kw;
        const float w01 = alpha * (1.f - beta) * kw;
        const float w10 = (1.f - alpha) * beta * kw;
        const float w11 = alpha * beta * kw;

        const int i00 = (ry0 << 10) + rx0;
        const int i01 = (ry0 << 10) + rx1;
        const int i10 = (ry1 << 10) + rx0;
        const int i11 = (ry1 << 10) + rx1;

        {
            const uint2 v = __ldg(imgb + i00);
            const float2 lo = __half22float2(*(__half2*)&v.x);
            const float2 hi = __half22float2(*(__half2*)&v.y);
            acc0 = fmaf(w00, lo.x, acc0);
            acc1 = fmaf(w00, lo.y, acc1);
            acc2 = fmaf(w00, hi.x, acc2);
        }
        {
            const uint2 v = __ldg(imgb + i01);
            const float2 lo = __half22float2(*(__half2*)&v.x);
            const float2 hi = __half22float2(*(__half2*)&v.y);
            acc0 = fmaf(w01, lo.x, acc0);
            acc1 = fmaf(w01, lo.y, acc1);
            acc2 = fmaf(w01, hi.x, acc2);
        }
        {
            const uint2 v = __ldg(imgb + i10);
            const float2 lo = __half22float2(*(__half2*)&v.x);
            const float2 hi = __half22float2(*(__half2*)&v.y);
            acc0 = fmaf(w10, lo.x, acc0);
            acc1 = fmaf(w10, lo.y, acc1);
            acc2 = fmaf(w10, hi.x, acc2);
        }
        {
            const uint2 v = __ldg(imgb + i11);
            const float2 lo = __half22float2(*(__half2*)&v.x);
            const float2 hi = __half22float2(*(__half2*)&v.y);
            acc0 = fmaf(w11, lo.x, acc0);
            acc1 = fmaf(w11, lo.y, acc1);
            acc2 = fmaf(w11, hi.x, acc2);
        }
    }

    const int ob = b * C_ * plane + pix;
    out[ob]             = acc0;
    out[ob + plane]     = acc1;
    out[ob + 2 * plane] = acc2;
}

extern "C" void kernel_launch(void* const* d_in, const int* in_sizes, int n_in,
                              void* d_out, int out_size) {
    const float* img     = (const float*)d_in[0];
    const float* kernels = (const float*)d_in[1];
    const float* offs_h  = (const float*)d_in[2];
    const float* offs_v  = (const float*)d_in[3];
    const float* ou      = (const float*)d_in[4];
    float* out = (float*)d_out;

    // One-time creation of side stream + events (created on the first,
    // uncaptured, correctness call; captured calls only record/wait/launch).
    static cudaStream_t s1 = nullptr;
    static cudaEvent_t evA = nullptr, evB = nullptr, evDone = nullptr;
    if (s1 == nullptr) {
        cudaStreamCreateWithFlags(&s1, cudaStreamNonBlocking);
        cudaEventCreateWithFlags(&evA, cudaEventDisableTiming);
        cudaEventCreateWithFlags(&evB, cudaEventDisableTiming);
        cudaEventCreateWithFlags(&evDone, cudaEventDisableTiming);
    }

    const int pre_blocks = BCHUNK_ * PLANE_ / 4 / 256;  // 4096 CTAs per chunk
    dim3 mblock(32, 8, 1);
    dim3 mgrid(WO_ / 32, HO_ / 8, BCHUNK_);             // 1024 CTAs per chunk

    // Chunk A: batches 0-3 ; Chunk B: batches 4-7.
    nchw_to_nhwc4h_kernel<<<pre_blocks, 256, 0, 0>>>(img, 0);
    cudaEventRecord(evA, 0);
    nchw_to_nhwc4h_kernel<<<pre_blocks, 256, 0, 0>>>(img, BCHUNK_);
    cudaEventRecord(evB, 0);

    cudaStreamWaitEvent(s1, evA, 0);
    adaptive_downsample_kernel<<<mgrid, mblock, 0, s1>>>(
        kernels, offs_h, offs_v, ou, out, 0);
    cudaStreamWaitEvent(s1, evB, 0);
    adaptive_downsample_kernel<<<mgrid, mblock, 0, s1>>>(
        kernels, offs_h, offs_v, ou, out, BCHUNK_);

    cudaEventRecord(evDone, s1);
    cudaStreamWaitEvent(0, evDone, 0);
}